// round 10
// baseline (speedup 1.0000x reference)
#include <cuda_runtime.h>
#include <cuda_bf16.h>

// Batched Kalman update: B=262144, DX=8, DZ=4.  TWO threads per batch.
// Pair = lanes (2m, 2m+1). Thread h owns rows h0:{0,1,2,3}, h1:{6,7,4,5}
// (rotation keeps simultaneous pair smem accesses conflict-free, SREG=19).
//
// W-form math (== Joseph form for the optimal gain):
//   PHT = P H^T, S = H PHT + R = L L^T;  W = PHT L^-T,  u = L^-1 y
//   x_new = x + W u,  P_new = P - W W^T
//
// vs R8:
//  * staging remapped to m=(t>>4)+8k, f=t&15: every 8-lane phase stays inside
//    one record -> conflict-free STS.128, gmem still fully coalesced.
//  * persistent grid (152 SM * 8 blocks = 1216) looping over tiles: removes
//    wave-transition overhead; H/R staged once per block.

#define NT   128
#define BPB  64
#define SREG 19
#define PGRID 1216   // 152 SMs * 8 resident blocks (GB300)

__global__ void __launch_bounds__(NT, 8) kalman_kernel(
    const float4* __restrict__ x4,
    const float4* __restrict__ z4,
    const float4* __restrict__ P4,
    const float*  __restrict__ Hg,
    const float*  __restrict__ Rg,
    float4*       __restrict__ out4,
    int nb)
{
    __shared__ float4 Buf4[BPB * SREG];   // 19456 B: [x(2q)|P(16q)|pad] per batch
    __shared__ float4 HT4[8];             // HT4[k] = H[0..3][k]
    __shared__ float  Rs[16];

    const int t  = threadIdx.x;
    const int hw = t >> 4;                // half-warp id 0..7
    const int fq = t & 15;                // quad-in-record

    if (t < 8)  HT4[t] = make_float4(Hg[t], Hg[8 + t], Hg[16 + t], Hg[24 + t]);
    if (t >= 32 && t < 48) Rs[t - 32] = Rg[t - 32];

    const int nblk = (nb + BPB - 1) / BPB;

    for (int blk = blockIdx.x; blk < nblk; blk += PGRID) {
        const int b0  = blk * BPB;
        const int nbb = min(BPB, nb - b0);

        __syncthreads();   // Buf4 reuse: prior drain reads must be done

        // ---- Stage P: coalesced LDG.128, conflict-free STS.128 ----
        // warp covers 32 consecutive gmem quads; each 8-lane phase writes
        // consecutive smem quads within one record.
        #pragma unroll
        for (int k = 0; k < 8; k++) {
            int m = hw + 8 * k;
            if (m < nbb)
                Buf4[m * SREG + 2 + fq] = P4[(size_t)b0 * 16 + 16 * m + fq];
        }

        // ---- Direct loads: x quad lands on its owner; z duplicated per pair ----
        float4 xq = make_float4(0.f, 0.f, 0.f, 0.f);
        float4 zq = make_float4(0.f, 0.f, 0.f, 0.f);
        if (t < 2 * nbb) {
            xq = x4[(size_t)b0 * 2 + t];
            zq = z4[b0 + (t >> 1)];
        }

        __syncthreads();

        if (t < 2 * nbb) {
            const int m  = t >> 1;
            const int h  = t & 1;
            const int rb = m * SREG;
            const unsigned FM = 0xffffffffu;

            // own rows: h0 -> 0,1,2,3 ; h1 -> 6,7,4,5
            int rown[4];
            #pragma unroll
            for (int i = 0; i < 4; i++) rown[i] = 4 * h + ((i + 2 * h) & 3);

            // ---- y = z - H x (pair-partial) ----
            float xo0 = xq.x, xo1 = xq.y, xo2 = xq.z, xo3 = xq.w;
            float s0, s1, s2, s3;
            {
                float4 ha = HT4[4 * h + 0], hb = HT4[4 * h + 1];
                float4 hc = HT4[4 * h + 2], hd = HT4[4 * h + 3];
                s0 = ha.x * xo0 + hb.x * xo1 + hc.x * xo2 + hd.x * xo3;
                s1 = ha.y * xo0 + hb.y * xo1 + hc.y * xo2 + hd.y * xo3;
                s2 = ha.z * xo0 + hb.z * xo1 + hc.z * xo2 + hd.z * xo3;
                s3 = ha.w * xo0 + hb.w * xo1 + hc.w * xo2 + hd.w * xo3;
            }
            float y0 = zq.x - (s0 + __shfl_xor_sync(FM, s0, 1));
            float y1 = zq.y - (s1 + __shfl_xor_sync(FM, s1, 1));
            float y2 = zq.z - (s2 + __shfl_xor_sync(FM, s2, 1));
            float y3 = zq.w - (s3 + __shfl_xor_sync(FM, s3, 1));

            // ---- W = PHT (own rows, row-wise) ----
            float W[4][4];
            #pragma unroll
            for (int i = 0; i < 4; i++) {
                int r = rown[i];
                float4 pa = Buf4[rb + 2 + 2 * r];
                float4 pb = Buf4[rb + 3 + 2 * r];
                float q0, q1, q2, q3;
                {
                    float4 h0q = HT4[0], h1q = HT4[1], h2q = HT4[2], h3q = HT4[3];
                    q0 = pa.x * h0q.x + pa.y * h1q.x + pa.z * h2q.x + pa.w * h3q.x;
                    q1 = pa.x * h0q.y + pa.y * h1q.y + pa.z * h2q.y + pa.w * h3q.y;
                    q2 = pa.x * h0q.z + pa.y * h1q.z + pa.z * h2q.z + pa.w * h3q.z;
                    q3 = pa.x * h0q.w + pa.y * h1q.w + pa.z * h2q.w + pa.w * h3q.w;
                }
                {
                    float4 h4q = HT4[4], h5q = HT4[5], h6q = HT4[6], h7q = HT4[7];
                    q0 += pb.x * h4q.x + pb.y * h5q.x + pb.z * h6q.x + pb.w * h7q.x;
                    q1 += pb.x * h4q.y + pb.y * h5q.y + pb.z * h6q.y + pb.w * h7q.y;
                    q2 += pb.x * h4q.z + pb.y * h5q.z + pb.z * h6q.z + pb.w * h7q.z;
                    q3 += pb.x * h4q.w + pb.y * h5q.w + pb.z * h6q.w + pb.w * h7q.w;
                }
                W[i][0] = q0; W[i][1] = q1; W[i][2] = q2; W[i][3] = q3;
            }

            // ---- S partial from own rows, then pair-reduce ----
            float S00 = 0.f, S01 = 0.f, S02 = 0.f, S03 = 0.f;
            float S11 = 0.f, S12 = 0.f, S13 = 0.f;
            float S22 = 0.f, S23 = 0.f, S33 = 0.f;
            #pragma unroll
            for (int i = 0; i < 4; i++) {
                float4 ht = HT4[rown[i]];
                float q0 = W[i][0], q1 = W[i][1], q2 = W[i][2], q3 = W[i][3];
                S00 += ht.x * q0; S01 += ht.x * q1; S02 += ht.x * q2; S03 += ht.x * q3;
                S11 += ht.y * q1; S12 += ht.y * q2; S13 += ht.y * q3;
                S22 += ht.z * q2; S23 += ht.z * q3;
                S33 += ht.w * q3;
            }
            S00 += __shfl_xor_sync(FM, S00, 1); S01 += __shfl_xor_sync(FM, S01, 1);
            S02 += __shfl_xor_sync(FM, S02, 1); S03 += __shfl_xor_sync(FM, S03, 1);
            S11 += __shfl_xor_sync(FM, S11, 1); S12 += __shfl_xor_sync(FM, S12, 1);
            S13 += __shfl_xor_sync(FM, S13, 1); S22 += __shfl_xor_sync(FM, S22, 1);
            S23 += __shfl_xor_sync(FM, S23, 1); S33 += __shfl_xor_sync(FM, S33, 1);
            S00 += Rs[0];  S01 += Rs[1];  S02 += Rs[2];  S03 += Rs[3];
            S11 += Rs[5];  S12 += Rs[6];  S13 += Rs[7];
            S22 += Rs[10]; S23 += Rs[11]; S33 += Rs[15];

            // ---- Cholesky ----
            float i0  = rsqrtf(S00);
            float l10 = S01 * i0, l20 = S02 * i0, l30 = S03 * i0;
            float i1  = rsqrtf(S11 - l10 * l10);
            float l21 = (S12 - l20 * l10) * i1;
            float l31 = (S13 - l30 * l10) * i1;
            float i2  = rsqrtf(S22 - l20 * l20 - l21 * l21);
            float l32 = (S23 - l30 * l20 - l31 * l21) * i2;
            float i3  = rsqrtf(S33 - l30 * l30 - l31 * l31 - l32 * l32);

            // ---- W <- W L^-T ----
            #pragma unroll
            for (int i = 0; i < 4; i++) {
                float w0 = W[i][0] * i0;
                float w1 = (W[i][1] - l10 * w0) * i1;
                float w2 = (W[i][2] - l20 * w0 - l21 * w1) * i2;
                float w3 = (W[i][3] - l30 * w0 - l31 * w1 - l32 * w2) * i3;
                W[i][0] = w0; W[i][1] = w1; W[i][2] = w2; W[i][3] = w3;
            }

            // ---- u = L^-1 y ----
            float u0 = y0 * i0;
            float u1 = (y1 - l10 * u0) * i1;
            float u2 = (y2 - l20 * u0 - l21 * u1) * i2;
            float u3 = (y3 - l30 * u0 - l31 * u1 - l32 * u2) * i3;

            // ---- x_new own quad (h1: elem kk -> slot (kk+2)&3) ----
            {
                float v0 = W[0][0] * u0 + W[0][1] * u1 + W[0][2] * u2 + W[0][3] * u3;
                float v1 = W[1][0] * u0 + W[1][1] * u1 + W[1][2] * u2 + W[1][3] * u3;
                float v2 = W[2][0] * u0 + W[2][1] * u1 + W[2][2] * u2 + W[2][3] * u3;
                float v3 = W[3][0] * u0 + W[3][1] * u1 + W[3][2] * u2 + W[3][3] * u3;
                float e0 = h ? v2 : v0, e1 = h ? v3 : v1;
                float e2 = h ? v0 : v2, e3 = h ? v1 : v3;
                Buf4[rb + h] = make_float4(xo0 + e0, xo1 + e1, xo2 + e2, xo3 + e3);
            }

            // ---- Partner W via 16 xor-shuffles ----
            float pW[4][4];
            #pragma unroll
            for (int s = 0; s < 4; s++)
                #pragma unroll
                for (int c = 0; c < 4; c++)
                    pW[s][c] = __shfl_xor_sync(FM, W[s][c], 1);

            // ---- P_new = P - W W^T, two 2-row halves (regs <= 64) ----
            #pragma unroll
            for (int half = 0; half < 2; half++) {
                float po[2][8];
                #pragma unroll
                for (int ii = 0; ii < 2; ii++) {
                    int r = rown[2 * half + ii];
                    float4 pa = Buf4[rb + 2 + 2 * r];
                    float4 pb = Buf4[rb + 3 + 2 * r];
                    po[ii][0] = pa.x; po[ii][1] = pa.y; po[ii][2] = pa.z; po[ii][3] = pa.w;
                    po[ii][4] = pb.x; po[ii][5] = pb.y; po[ii][6] = pb.z; po[ii][7] = pb.w;
                }
                #pragma unroll
                for (int g = 0; g < 8; g++) {
                    const int slot = (g < 4) ? g : ((g + 2) & 3);
                    float wg0, wg1, wg2, wg3;
                    if (g < 4) {
                        wg0 = h ? pW[slot][0] : W[slot][0];
                        wg1 = h ? pW[slot][1] : W[slot][1];
                        wg2 = h ? pW[slot][2] : W[slot][2];
                        wg3 = h ? pW[slot][3] : W[slot][3];
                    } else {
                        wg0 = h ? W[slot][0] : pW[slot][0];
                        wg1 = h ? W[slot][1] : pW[slot][1];
                        wg2 = h ? W[slot][2] : pW[slot][2];
                        wg3 = h ? W[slot][3] : pW[slot][3];
                    }
                    #pragma unroll
                    for (int ii = 0; ii < 2; ii++) {
                        int s = 2 * half + ii;
                        po[ii][g] -= W[s][0] * wg0 + W[s][1] * wg1
                                   + W[s][2] * wg2 + W[s][3] * wg3;
                    }
                }
                #pragma unroll
                for (int ii = 0; ii < 2; ii++) {
                    int r = rown[2 * half + ii];
                    Buf4[rb + 2 + 2 * r] = make_float4(po[ii][0], po[ii][1], po[ii][2], po[ii][3]);
                    Buf4[rb + 3 + 2 * r] = make_float4(po[ii][4], po[ii][5], po[ii][6], po[ii][7]);
                }
            }
        }

        __syncthreads();

        // ---- Drain: quads 0..17 of each region are the output record ----
        {
            const int total = nbb * 18;
            #pragma unroll
            for (int k = 0; k < 9; k++) {
                int idx = t + NT * k;
                if (idx < total) {
                    int mm = idx / 18;
                    int j  = idx - mm * 18;
                    out4[(size_t)b0 * 18 + idx] = Buf4[mm * SREG + j];
                }
            }
        }
    }
}

extern "C" void kernel_launch(void* const* d_in, const int* in_sizes, int n_in,
                              void* d_out, int out_size) {
    const float4* x4 = (const float4*)d_in[0];
    const float4* z4 = (const float4*)d_in[1];
    const float4* P4 = (const float4*)d_in[2];
    const float*  Hg = (const float*)d_in[3];
    const float*  Rg = (const float*)d_in[4];
    float4* out4 = (float4*)d_out;

    int nb = in_sizes[0] / 8;            // B
    int nblk = (nb + BPB - 1) / BPB;
    int grid = nblk < PGRID ? nblk : PGRID;
    kalman_kernel<<<grid, NT>>>(x4, z4, P4, Hg, Rg, out4, nb);
}

// round 11
// speedup vs baseline: 1.0703x; 1.0703x over previous
#include <cuda_runtime.h>
#include <cuda_bf16.h>

// Batched Kalman update: B=262144, DX=8, DZ=4.  TWO threads per batch.
// Pair = lanes (2m, 2m+1). Thread h owns rows h0:{0,1,2,3}, h1:{6,7,4,5}
// (rotation keeps simultaneous pair smem accesses conflict-free, SREG=19).
//
// W-form math (== Joseph form for the optimal gain):
//   PHT = P H^T, S = H PHT + R = L L^T;  W = PHT L^-T,  u = L^-1 y
//   x_new = x + W u,  P_new = P - W W^T
//
// == R8 (best) + ONE delta: P staging remapped to m=hw+8k, f=t&15 so each
// 8-lane STS phase writes consecutive quads inside one record (bank-conflict
// free) while each warp still loads 32 consecutive gmem quads (coalesced).
// Persistence from R10 reverted (it serialized phases and lost overlap).

#define NT   128
#define BPB  64
#define SREG 19

__global__ void __launch_bounds__(NT, 8) kalman_kernel(
    const float4* __restrict__ x4,
    const float4* __restrict__ z4,
    const float4* __restrict__ P4,
    const float*  __restrict__ Hg,
    const float*  __restrict__ Rg,
    float4*       __restrict__ out4,
    int nb)
{
    __shared__ float4 Buf4[BPB * SREG];   // 19456 B: [x(2q)|P(16q)|pad] per batch
    __shared__ float4 HT4[8];             // HT4[k] = H[0..3][k]
    __shared__ float  Rs[16];

    const int t   = threadIdx.x;
    const int b0  = blockIdx.x * BPB;
    const int nbb = min(BPB, nb - b0);

    if (t < 8)  HT4[t] = make_float4(Hg[t], Hg[8 + t], Hg[16 + t], Hg[24 + t]);
    if (t >= 32 && t < 48) Rs[t - 32] = Rg[t - 32];

    // ---- Stage P: coalesced LDG.128, conflict-free STS.128 ----
    // m = hw + 8k: each 8-lane phase writes consecutive quads of one record;
    // warp covers gmem quads [128k + 16*hw, +32) -> fully coalesced.
    {
        const int hw = t >> 4;            // half-warp id 0..7
        const int fq = t & 15;            // quad-in-record
        #pragma unroll
        for (int k = 0; k < 8; k++) {
            int m = hw + 8 * k;
            if (m < nbb)
                Buf4[m * SREG + 2 + fq] = P4[(size_t)b0 * 16 + 16 * m + fq];
        }
    }

    // ---- Direct loads: x quad lands on its owner; z duplicated per pair ----
    float4 xq = make_float4(0.f, 0.f, 0.f, 0.f);
    float4 zq = make_float4(0.f, 0.f, 0.f, 0.f);
    if (t < 2 * nbb) {
        xq = x4[(size_t)b0 * 2 + t];
        zq = z4[b0 + (t >> 1)];
    }

    __syncthreads();

    if (t < 2 * nbb) {
        const int m  = t >> 1;
        const int h  = t & 1;
        const int rb = m * SREG;
        const unsigned FM = 0xffffffffu;

        // own rows: h0 -> 0,1,2,3 ; h1 -> 6,7,4,5
        int rown[4];
        #pragma unroll
        for (int i = 0; i < 4; i++) rown[i] = 4 * h + ((i + 2 * h) & 3);

        // ---- y = z - H x (pair-partial) ----
        float xo0 = xq.x, xo1 = xq.y, xo2 = xq.z, xo3 = xq.w;
        float s0, s1, s2, s3;
        {
            float4 ha = HT4[4 * h + 0], hb = HT4[4 * h + 1];
            float4 hc = HT4[4 * h + 2], hd = HT4[4 * h + 3];
            s0 = ha.x * xo0 + hb.x * xo1 + hc.x * xo2 + hd.x * xo3;
            s1 = ha.y * xo0 + hb.y * xo1 + hc.y * xo2 + hd.y * xo3;
            s2 = ha.z * xo0 + hb.z * xo1 + hc.z * xo2 + hd.z * xo3;
            s3 = ha.w * xo0 + hb.w * xo1 + hc.w * xo2 + hd.w * xo3;
        }
        float y0 = zq.x - (s0 + __shfl_xor_sync(FM, s0, 1));
        float y1 = zq.y - (s1 + __shfl_xor_sync(FM, s1, 1));
        float y2 = zq.z - (s2 + __shfl_xor_sync(FM, s2, 1));
        float y3 = zq.w - (s3 + __shfl_xor_sync(FM, s3, 1));

        // ---- W = PHT (own rows, row-wise: one P row live at a time) ----
        float W[4][4];
        #pragma unroll
        for (int i = 0; i < 4; i++) {
            int r = rown[i];
            float4 pa = Buf4[rb + 2 + 2 * r];
            float4 pb = Buf4[rb + 3 + 2 * r];
            float q0, q1, q2, q3;
            {
                float4 h0q = HT4[0], h1q = HT4[1], h2q = HT4[2], h3q = HT4[3];
                q0 = pa.x * h0q.x + pa.y * h1q.x + pa.z * h2q.x + pa.w * h3q.x;
                q1 = pa.x * h0q.y + pa.y * h1q.y + pa.z * h2q.y + pa.w * h3q.y;
                q2 = pa.x * h0q.z + pa.y * h1q.z + pa.z * h2q.z + pa.w * h3q.z;
                q3 = pa.x * h0q.w + pa.y * h1q.w + pa.z * h2q.w + pa.w * h3q.w;
            }
            {
                float4 h4q = HT4[4], h5q = HT4[5], h6q = HT4[6], h7q = HT4[7];
                q0 += pb.x * h4q.x + pb.y * h5q.x + pb.z * h6q.x + pb.w * h7q.x;
                q1 += pb.x * h4q.y + pb.y * h5q.y + pb.z * h6q.y + pb.w * h7q.y;
                q2 += pb.x * h4q.z + pb.y * h5q.z + pb.z * h6q.z + pb.w * h7q.z;
                q3 += pb.x * h4q.w + pb.y * h5q.w + pb.z * h6q.w + pb.w * h7q.w;
            }
            W[i][0] = q0; W[i][1] = q1; W[i][2] = q2; W[i][3] = q3;
        }

        // ---- S partial from own rows, then pair-reduce ----
        float S00 = 0.f, S01 = 0.f, S02 = 0.f, S03 = 0.f;
        float S11 = 0.f, S12 = 0.f, S13 = 0.f;
        float S22 = 0.f, S23 = 0.f, S33 = 0.f;
        #pragma unroll
        for (int i = 0; i < 4; i++) {
            float4 ht = HT4[rown[i]];
            float q0 = W[i][0], q1 = W[i][1], q2 = W[i][2], q3 = W[i][3];
            S00 += ht.x * q0; S01 += ht.x * q1; S02 += ht.x * q2; S03 += ht.x * q3;
            S11 += ht.y * q1; S12 += ht.y * q2; S13 += ht.y * q3;
            S22 += ht.z * q2; S23 += ht.z * q3;
            S33 += ht.w * q3;
        }
        S00 += __shfl_xor_sync(FM, S00, 1); S01 += __shfl_xor_sync(FM, S01, 1);
        S02 += __shfl_xor_sync(FM, S02, 1); S03 += __shfl_xor_sync(FM, S03, 1);
        S11 += __shfl_xor_sync(FM, S11, 1); S12 += __shfl_xor_sync(FM, S12, 1);
        S13 += __shfl_xor_sync(FM, S13, 1); S22 += __shfl_xor_sync(FM, S22, 1);
        S23 += __shfl_xor_sync(FM, S23, 1); S33 += __shfl_xor_sync(FM, S33, 1);
        S00 += Rs[0];  S01 += Rs[1];  S02 += Rs[2];  S03 += Rs[3];
        S11 += Rs[5];  S12 += Rs[6];  S13 += Rs[7];
        S22 += Rs[10]; S23 += Rs[11]; S33 += Rs[15];

        // ---- Cholesky ----
        float i0  = rsqrtf(S00);
        float l10 = S01 * i0, l20 = S02 * i0, l30 = S03 * i0;
        float i1  = rsqrtf(S11 - l10 * l10);
        float l21 = (S12 - l20 * l10) * i1;
        float l31 = (S13 - l30 * l10) * i1;
        float i2  = rsqrtf(S22 - l20 * l20 - l21 * l21);
        float l32 = (S23 - l30 * l20 - l31 * l21) * i2;
        float i3  = rsqrtf(S33 - l30 * l30 - l31 * l31 - l32 * l32);

        // ---- W <- W L^-T ----
        #pragma unroll
        for (int i = 0; i < 4; i++) {
            float w0 = W[i][0] * i0;
            float w1 = (W[i][1] - l10 * w0) * i1;
            float w2 = (W[i][2] - l20 * w0 - l21 * w1) * i2;
            float w3 = (W[i][3] - l30 * w0 - l31 * w1 - l32 * w2) * i3;
            W[i][0] = w0; W[i][1] = w1; W[i][2] = w2; W[i][3] = w3;
        }

        // ---- u = L^-1 y ----
        float u0 = y0 * i0;
        float u1 = (y1 - l10 * u0) * i1;
        float u2 = (y2 - l20 * u0 - l21 * u1) * i2;
        float u3 = (y3 - l30 * u0 - l31 * u1 - l32 * u2) * i3;

        // ---- x_new own quad (h1: elem kk -> slot (kk+2)&3) ----
        {
            float v0 = W[0][0] * u0 + W[0][1] * u1 + W[0][2] * u2 + W[0][3] * u3;
            float v1 = W[1][0] * u0 + W[1][1] * u1 + W[1][2] * u2 + W[1][3] * u3;
            float v2 = W[2][0] * u0 + W[2][1] * u1 + W[2][2] * u2 + W[2][3] * u3;
            float v3 = W[3][0] * u0 + W[3][1] * u1 + W[3][2] * u2 + W[3][3] * u3;
            float e0 = h ? v2 : v0, e1 = h ? v3 : v1;
            float e2 = h ? v0 : v2, e3 = h ? v1 : v3;
            Buf4[rb + h] = make_float4(xo0 + e0, xo1 + e1, xo2 + e2, xo3 + e3);
        }

        // ---- Partner W via 16 xor-shuffles (S/chol regs now dead) ----
        float pW[4][4];
        #pragma unroll
        for (int s = 0; s < 4; s++)
            #pragma unroll
            for (int c = 0; c < 4; c++)
                pW[s][c] = __shfl_xor_sync(FM, W[s][c], 1);

        // ---- P_new = P - W W^T, two 2-row halves (regs <= 64) ----
        #pragma unroll
        for (int half = 0; half < 2; half++) {
            float po[2][8];
            #pragma unroll
            for (int ii = 0; ii < 2; ii++) {
                int r = rown[2 * half + ii];
                float4 pa = Buf4[rb + 2 + 2 * r];
                float4 pb = Buf4[rb + 3 + 2 * r];
                po[ii][0] = pa.x; po[ii][1] = pa.y; po[ii][2] = pa.z; po[ii][3] = pa.w;
                po[ii][4] = pb.x; po[ii][5] = pb.y; po[ii][6] = pb.z; po[ii][7] = pb.w;
            }
            #pragma unroll
            for (int g = 0; g < 8; g++) {
                const int slot = (g < 4) ? g : ((g + 2) & 3);  // owner's W slot
                float wg0, wg1, wg2, wg3;
                if (g < 4) {  // rows 0..3 owned by h0
                    wg0 = h ? pW[slot][0] : W[slot][0];
                    wg1 = h ? pW[slot][1] : W[slot][1];
                    wg2 = h ? pW[slot][2] : W[slot][2];
                    wg3 = h ? pW[slot][3] : W[slot][3];
                } else {      // rows 4..7 owned by h1
                    wg0 = h ? W[slot][0] : pW[slot][0];
                    wg1 = h ? W[slot][1] : pW[slot][1];
                    wg2 = h ? W[slot][2] : pW[slot][2];
                    wg3 = h ? W[slot][3] : pW[slot][3];
                }
                #pragma unroll
                for (int ii = 0; ii < 2; ii++) {
                    int s = 2 * half + ii;
                    po[ii][g] -= W[s][0] * wg0 + W[s][1] * wg1
                               + W[s][2] * wg2 + W[s][3] * wg3;
                }
            }
            #pragma unroll
            for (int ii = 0; ii < 2; ii++) {
                int r = rown[2 * half + ii];
                Buf4[rb + 2 + 2 * r] = make_float4(po[ii][0], po[ii][1], po[ii][2], po[ii][3]);
                Buf4[rb + 3 + 2 * r] = make_float4(po[ii][4], po[ii][5], po[ii][6], po[ii][7]);
            }
        }
    }

    __syncthreads();

    // ---- Drain: quads 0..17 of each region are exactly the output record ----
    {
        const int total = nbb * 18;
        #pragma unroll
        for (int k = 0; k < 9; k++) {
            int idx = t + NT * k;
            if (idx < total) {
                int mm = idx / 18;
                int j  = idx - mm * 18;
                out4[(size_t)b0 * 18 + idx] = Buf4[mm * SREG + j];
            }
        }
    }
}

extern "C" void kernel_launch(void* const* d_in, const int* in_sizes, int n_in,
                              void* d_out, int out_size) {
    const float4* x4 = (const float4*)d_in[0];
    const float4* z4 = (const float4*)d_in[1];
    const float4* P4 = (const float4*)d_in[2];
    const float*  Hg = (const float*)d_in[3];
    const float*  Rg = (const float*)d_in[4];
    float4* out4 = (float4*)d_out;

    int nb = in_sizes[0] / 8;            // B
    int grid = (nb + BPB - 1) / BPB;
    kalman_kernel<<<grid, NT>>>(x4, z4, P4, Hg, Rg, out4, nb);
}

// round 12
// speedup vs baseline: 1.2087x; 1.1293x over previous
#include <cuda_runtime.h>
#include <cuda_bf16.h>

// Batched Kalman update: B=262144, DX=8, DZ=4.  TWO threads per batch.
// Pair = lanes (2m, 2m+1); thread h owns rows 4h..4h+3 (no rotation).
//
// Conflict-free even-stride trick (SREG=18): every row access loads/stores
// its two quads in h-swapped order -- Buf4[A+h] then Buf4[A+1-h] -- so h0
// lanes always touch even quads while h1 lanes touch odd quads in the same
// instruction; with stride 18 (mod 8 = 2) the 8-lane phase addresses are
// {even set} U {odd set}: disjoint -> no bank conflicts.
// Consequence: qa always holds cols 4h..4h+3 (own-row cols), so all W/pW
// epilogue indices are STATIC (no h-selects at all).
//
// SREG=18 => region == output record [x(2q)|P(16q)] and the block's results
// are one contiguous 18KB span: drained with a single cp.async.bulk via the
// TMA pipe (removes the LDS+STG drain from the saturated L1 pipe).
//
// W-form math (== Joseph form for the optimal gain):
//   PHT = P H^T, S = H PHT + R = L L^T;  W = PHT L^-T,  u = L^-1 y
//   x_new = x + W u,  P_new = P - W W^T

#define NT   128
#define BPB  64
#define SREG 18

__global__ void __launch_bounds__(NT, 8) kalman_kernel(
    const float4* __restrict__ x4,
    const float4* __restrict__ z4,
    const float4* __restrict__ P4,
    const float*  __restrict__ Hg,
    const float*  __restrict__ Rg,
    float4*       __restrict__ out4,
    int nb)
{
    __shared__ float4 Buf4[BPB * SREG];   // 18432 B, contiguous output image
    __shared__ float4 HT4[8];             // HT4[k] = H[0..3][k]
    __shared__ float  Rs[16];

    const int t   = threadIdx.x;
    const int b0  = blockIdx.x * BPB;
    const int nbb = min(BPB, nb - b0);

    if (t < 8)  HT4[t] = make_float4(Hg[t], Hg[8 + t], Hg[16 + t], Hg[24 + t]);
    if (t >= 32 && t < 48) Rs[t - 32] = Rg[t - 32];

    // ---- Stage P: coalesced LDG.128, conflict-free STS.128 ----
    // m = hw + 8k: each 8-lane phase writes consecutive quads of one record.
    {
        const int hw = t >> 4;            // half-warp id 0..7
        const int fq = t & 15;            // quad-in-record
        #pragma unroll
        for (int k = 0; k < 8; k++) {
            int m = hw + 8 * k;
            if (m < nbb)
                Buf4[m * SREG + 2 + fq] = P4[(size_t)b0 * 16 + 16 * m + fq];
        }
    }

    // ---- Direct loads: x quad (elems 4h..4h+3) on its owner; z per pair ----
    float4 xq = make_float4(0.f, 0.f, 0.f, 0.f);
    float4 zq = make_float4(0.f, 0.f, 0.f, 0.f);
    if (t < 2 * nbb) {
        xq = x4[(size_t)b0 * 2 + t];
        zq = z4[b0 + (t >> 1)];
    }

    __syncthreads();

    if (t < 2 * nbb) {
        const int m  = t >> 1;
        const int h  = t & 1;
        const int rb = m * SREG;
        const int hb1 = 4 * h;            // HT base for qa cols
        const int hb2 = 4 - 4 * h;        // HT base for qb cols
        const unsigned FM = 0xffffffffu;

        // ---- y = z - H x (pair-partial; own elems are cols 4h..4h+3) ----
        float xo0 = xq.x, xo1 = xq.y, xo2 = xq.z, xo3 = xq.w;
        float s0, s1, s2, s3;
        {
            float4 ha = HT4[hb1 + 0], hb = HT4[hb1 + 1];
            float4 hc = HT4[hb1 + 2], hd = HT4[hb1 + 3];
            s0 = ha.x * xo0 + hb.x * xo1 + hc.x * xo2 + hd.x * xo3;
            s1 = ha.y * xo0 + hb.y * xo1 + hc.y * xo2 + hd.y * xo3;
            s2 = ha.z * xo0 + hb.z * xo1 + hc.z * xo2 + hd.z * xo3;
            s3 = ha.w * xo0 + hb.w * xo1 + hc.w * xo2 + hd.w * xo3;
        }
        float y0 = zq.x - (s0 + __shfl_xor_sync(FM, s0, 1));
        float y1 = zq.y - (s1 + __shfl_xor_sync(FM, s1, 1));
        float y2 = zq.z - (s2 + __shfl_xor_sync(FM, s2, 1));
        float y3 = zq.w - (s3 + __shfl_xor_sync(FM, s3, 1));

        // ---- W = PHT for own rows 4h+i (parity-swapped quad reads) ----
        float W[4][4];
        #pragma unroll
        for (int i = 0; i < 4; i++) {
            const int A = rb + 2 + 8 * h + 2 * i;   // quad pair base of row 4h+i
            float4 qa = Buf4[A + h];                // cols 4h..4h+3
            float4 qb = Buf4[A + 1 - h];            // cols 4(1-h)..
            float q0, q1, q2, q3;
            {
                float4 c0 = HT4[hb1 + 0], c1 = HT4[hb1 + 1];
                float4 c2 = HT4[hb1 + 2], c3 = HT4[hb1 + 3];
                q0 = qa.x * c0.x + qa.y * c1.x + qa.z * c2.x + qa.w * c3.x;
                q1 = qa.x * c0.y + qa.y * c1.y + qa.z * c2.y + qa.w * c3.y;
                q2 = qa.x * c0.z + qa.y * c1.z + qa.z * c2.z + qa.w * c3.z;
                q3 = qa.x * c0.w + qa.y * c1.w + qa.z * c2.w + qa.w * c3.w;
            }
            {
                float4 c0 = HT4[hb2 + 0], c1 = HT4[hb2 + 1];
                float4 c2 = HT4[hb2 + 2], c3 = HT4[hb2 + 3];
                q0 += qb.x * c0.x + qb.y * c1.x + qb.z * c2.x + qb.w * c3.x;
                q1 += qb.x * c0.y + qb.y * c1.y + qb.z * c2.y + qb.w * c3.y;
                q2 += qb.x * c0.z + qb.y * c1.z + qb.z * c2.z + qb.w * c3.z;
                q3 += qb.x * c0.w + qb.y * c1.w + qb.z * c2.w + qb.w * c3.w;
            }
            W[i][0] = q0; W[i][1] = q1; W[i][2] = q2; W[i][3] = q3;
        }

        // ---- S partial from own rows (row 4h+i -> HT4[4h+i]), pair-reduce ----
        float S00 = 0.f, S01 = 0.f, S02 = 0.f, S03 = 0.f;
        float S11 = 0.f, S12 = 0.f, S13 = 0.f;
        float S22 = 0.f, S23 = 0.f, S33 = 0.f;
        #pragma unroll
        for (int i = 0; i < 4; i++) {
            float4 ht = HT4[hb1 + i];
            float q0 = W[i][0], q1 = W[i][1], q2 = W[i][2], q3 = W[i][3];
            S00 += ht.x * q0; S01 += ht.x * q1; S02 += ht.x * q2; S03 += ht.x * q3;
            S11 += ht.y * q1; S12 += ht.y * q2; S13 += ht.y * q3;
            S22 += ht.z * q2; S23 += ht.z * q3;
            S33 += ht.w * q3;
        }
        S00 += __shfl_xor_sync(FM, S00, 1); S01 += __shfl_xor_sync(FM, S01, 1);
        S02 += __shfl_xor_sync(FM, S02, 1); S03 += __shfl_xor_sync(FM, S03, 1);
        S11 += __shfl_xor_sync(FM, S11, 1); S12 += __shfl_xor_sync(FM, S12, 1);
        S13 += __shfl_xor_sync(FM, S13, 1); S22 += __shfl_xor_sync(FM, S22, 1);
        S23 += __shfl_xor_sync(FM, S23, 1); S33 += __shfl_xor_sync(FM, S33, 1);
        S00 += Rs[0];  S01 += Rs[1];  S02 += Rs[2];  S03 += Rs[3];
        S11 += Rs[5];  S12 += Rs[6];  S13 += Rs[7];
        S22 += Rs[10]; S23 += Rs[11]; S33 += Rs[15];

        // ---- Cholesky ----
        float i0  = rsqrtf(S00);
        float l10 = S01 * i0, l20 = S02 * i0, l30 = S03 * i0;
        float i1  = rsqrtf(S11 - l10 * l10);
        float l21 = (S12 - l20 * l10) * i1;
        float l31 = (S13 - l30 * l10) * i1;
        float i2  = rsqrtf(S22 - l20 * l20 - l21 * l21);
        float l32 = (S23 - l30 * l20 - l31 * l21) * i2;
        float i3  = rsqrtf(S33 - l30 * l30 - l31 * l31 - l32 * l32);

        // ---- W <- W L^-T ----
        #pragma unroll
        for (int i = 0; i < 4; i++) {
            float w0 = W[i][0] * i0;
            float w1 = (W[i][1] - l10 * w0) * i1;
            float w2 = (W[i][2] - l20 * w0 - l21 * w1) * i2;
            float w3 = (W[i][3] - l30 * w0 - l31 * w1 - l32 * w2) * i3;
            W[i][0] = w0; W[i][1] = w1; W[i][2] = w2; W[i][3] = w3;
        }

        // ---- u = L^-1 y ----
        float u0 = y0 * i0;
        float u1 = (y1 - l10 * u0) * i1;
        float u2 = (y2 - l20 * u0 - l21 * u1) * i2;
        float u3 = (y3 - l30 * u0 - l31 * u1 - l32 * u2) * i3;

        // ---- x_new own quad: elem 4h+i pairs with own W[i] (static!) ----
        Buf4[rb + h] = make_float4(
            xo0 + W[0][0]*u0 + W[0][1]*u1 + W[0][2]*u2 + W[0][3]*u3,
            xo1 + W[1][0]*u0 + W[1][1]*u1 + W[1][2]*u2 + W[1][3]*u3,
            xo2 + W[2][0]*u0 + W[2][1]*u1 + W[2][2]*u2 + W[2][3]*u3,
            xo3 + W[3][0]*u0 + W[3][1]*u1 + W[3][2]*u2 + W[3][3]*u3);

        // ---- Partner W via 16 xor-shuffles: pW[s] = partner row 4(1-h)+s ----
        float pW[4][4];
        #pragma unroll
        for (int s = 0; s < 4; s++)
            #pragma unroll
            for (int c = 0; c < 4; c++)
                pW[s][c] = __shfl_xor_sync(FM, W[s][c], 1);

        // ---- P_new = P - W W^T, two 2-row halves; ALL indices static ----
        // po[c]   = col 4h+c     -> subtract W[i].W[c]   (own rows)
        // po[4+c] = col 4(1-h)+c -> subtract W[i].pW[c]  (partner rows)
        #pragma unroll
        for (int half = 0; half < 2; half++) {
            float po[2][8];
            #pragma unroll
            for (int ii = 0; ii < 2; ii++) {
                const int i = 2 * half + ii;
                const int A = rb + 2 + 8 * h + 2 * i;
                float4 qa = Buf4[A + h];
                float4 qb = Buf4[A + 1 - h];
                po[ii][0] = qa.x; po[ii][1] = qa.y; po[ii][2] = qa.z; po[ii][3] = qa.w;
                po[ii][4] = qb.x; po[ii][5] = qb.y; po[ii][6] = qb.z; po[ii][7] = qb.w;
            }
            #pragma unroll
            for (int ii = 0; ii < 2; ii++) {
                const int i = 2 * half + ii;
                float w0 = W[i][0], w1 = W[i][1], w2 = W[i][2], w3 = W[i][3];
                #pragma unroll
                for (int c = 0; c < 4; c++)
                    po[ii][c] -= w0 * W[c][0] + w1 * W[c][1]
                               + w2 * W[c][2] + w3 * W[c][3];
                #pragma unroll
                for (int c = 0; c < 4; c++)
                    po[ii][4 + c] -= w0 * pW[c][0] + w1 * pW[c][1]
                                   + w2 * pW[c][2] + w3 * pW[c][3];
            }
            #pragma unroll
            for (int ii = 0; ii < 2; ii++) {
                const int i = 2 * half + ii;
                const int A = rb + 2 + 8 * h + 2 * i;
                Buf4[A + h]     = make_float4(po[ii][0], po[ii][1], po[ii][2], po[ii][3]);
                Buf4[A + 1 - h] = make_float4(po[ii][4], po[ii][5], po[ii][6], po[ii][7]);
            }
        }
    }

    __syncthreads();

    // ---- Drain: one contiguous bulk copy SMEM -> GMEM via the TMA pipe ----
    if (t == 0) {
        unsigned sa = (unsigned)__cvta_generic_to_shared(&Buf4[0]);
        float4* gdst = out4 + (size_t)b0 * 18;
        int bytes = nbb * 18 * 16;
        asm volatile("fence.proxy.async.shared::cta;" ::: "memory");
        asm volatile(
            "cp.async.bulk.global.shared::cta.bulk_group [%0], [%1], %2;"
            :: "l"(gdst), "r"(sa), "r"(bytes) : "memory");
        asm volatile("cp.async.bulk.commit_group;" ::: "memory");
        asm volatile("cp.async.bulk.wait_group.read 0;" ::: "memory");
    }
}

extern "C" void kernel_launch(void* const* d_in, const int* in_sizes, int n_in,
                              void* d_out, int out_size) {
    const float4* x4 = (const float4*)d_in[0];
    const float4* z4 = (const float4*)d_in[1];
    const float4* P4 = (const float4*)d_in[2];
    const float*  Hg = (const float*)d_in[3];
    const float*  Rg = (const float*)d_in[4];
    float4* out4 = (float4*)d_out;

    int nb = in_sizes[0] / 8;            // B
    int grid = (nb + BPB - 1) / BPB;
    kalman_kernel<<<grid, NT>>>(x4, z4, P4, Hg, Rg, out4, nb);
}